// round 2
// baseline (speedup 1.0000x reference)
#include <cuda_runtime.h>
#include <stdint.h>

// Problem shape (fixed by the dataset): x,y are [4096, 3072] fp32, buffers length 50000.
#define D_DIM 3072
#define NB    4096

// Scratch (no cudaMalloc allowed -> __device__ globals)
__device__ float g_x2[NB];
__device__ float g_y2[NB];
__device__ unsigned long long g_best[NB];   // packed (float_bits(v) << 32) | col_index

// ---------------------------------------------------------------------------
// Row squared-norms for x (blocks [0,NB)) and y (blocks [NB,2NB))
// ---------------------------------------------------------------------------
__global__ void norms_kernel(const float* __restrict__ x, const float* __restrict__ y) {
    int row = blockIdx.x;
    const float* p = (row < NB) ? (x + (size_t)row * D_DIM)
                                : (y + (size_t)(row - NB) * D_DIM);
    const float4* p4 = (const float4*)p;
    float s = 0.f;
    #pragma unroll 3
    for (int k = threadIdx.x; k < D_DIM / 4; k += 256) {
        float4 v = p4[k];
        s += v.x * v.x + v.y * v.y + v.z * v.z + v.w * v.w;
    }
    __shared__ float sm[256];
    sm[threadIdx.x] = s;
    __syncthreads();
    for (int o = 128; o > 0; o >>= 1) {
        if (threadIdx.x < o) sm[threadIdx.x] += sm[threadIdx.x + o];
        __syncthreads();
    }
    if (threadIdx.x == 0) {
        if (row < NB) g_x2[row] = sm[0];
        else          g_y2[row - NB] = sm[0];
    }
}

// ---------------------------------------------------------------------------
// Copy passthrough outputs (out is poisoned) + reset the argmin scratch
// out[0:N)      = min_dists (float)
// out[N:2N)     = nn_indices converted to float
// ---------------------------------------------------------------------------
__global__ void init_out_kernel(const float* __restrict__ md, const int* __restrict__ ni,
                                float* __restrict__ out, int N) {
    int i = blockIdx.x * blockDim.x + threadIdx.x;
    if (i < N) {
        out[i]     = md[i];
        out[N + i] = (float)ni[i];
    }
    if (i < NB) g_best[i] = 0xFFFFFFFFFFFFFFFFULL;
}

// ---------------------------------------------------------------------------
// Fused GEMM + per-row (min, argmin) over v = y2[j] - 2*dot(x_i, y_j).
// 128x128 tile per block, 8x8 per thread, K-step 8, fp32 FFMA accumulation.
// ---------------------------------------------------------------------------
__global__ __launch_bounds__(256, 2)
void gemm_min_kernel(const float* __restrict__ X, const float* __restrict__ Y) {
    __shared__ float As[8][128];
    __shared__ float Bs[8][128];

    const int t  = threadIdx.x;
    const int tx = t & 15;        // 16 thread-cols
    const int ty = t >> 4;        // 16 thread-rows
    const int bm = blockIdx.y * 128;
    const int bn = blockIdx.x * 128;

    // Global-load assignment: 128 rows x 8 k, one float4 per thread per tile.
    const int lrow = t >> 1;            // 0..127
    const int kq4  = t & 1;             // which float4 of the 8-wide k chunk
    const float4* Xr = (const float4*)(X + (size_t)(bm + lrow) * D_DIM) + kq4;
    const float4* Yr = (const float4*)(Y + (size_t)(bn + lrow) * D_DIM) + kq4;

    float acc[8][8];
    #pragma unroll
    for (int i = 0; i < 8; i++)
        #pragma unroll
        for (int j = 0; j < 8; j++) acc[i][j] = 0.f;

    float4 xa = Xr[0];
    float4 yb = Yr[0];

    for (int k0 = 0; k0 < D_DIM; k0 += 8) {
        __syncthreads();                       // previous tile fully consumed
        const int ks = kq4 * 4;
        As[ks + 0][lrow] = xa.x; As[ks + 1][lrow] = xa.y;
        As[ks + 2][lrow] = xa.z; As[ks + 3][lrow] = xa.w;
        Bs[ks + 0][lrow] = yb.x; Bs[ks + 1][lrow] = yb.y;
        Bs[ks + 2][lrow] = yb.z; Bs[ks + 3][lrow] = yb.w;
        __syncthreads();

        if (k0 + 8 < D_DIM) {                  // prefetch next tile into regs
            xa = Xr[(k0 + 8) >> 2];
            yb = Yr[(k0 + 8) >> 2];
        }

        #pragma unroll
        for (int kk = 0; kk < 8; kk++) {
            float4 a0 = *(const float4*)&As[kk][ty * 8];
            float4 a1 = *(const float4*)&As[kk][ty * 8 + 4];
            float4 b0 = *(const float4*)&Bs[kk][tx * 8];
            float4 b1 = *(const float4*)&Bs[kk][tx * 8 + 4];
            float a[8] = {a0.x, a0.y, a0.z, a0.w, a1.x, a1.y, a1.z, a1.w};
            float b[8] = {b0.x, b0.y, b0.z, b0.w, b1.x, b1.y, b1.z, b1.w};
            #pragma unroll
            for (int i = 0; i < 8; i++)
                #pragma unroll
                for (int j = 0; j < 8; j++)
                    acc[i][j] = fmaf(a[i], b[j], acc[i][j]);
        }
    }

    // Epilogue: per-row min over this block's 128 columns, then global atomicMin.
    float y2r[8];
    #pragma unroll
    for (int j = 0; j < 8; j++) y2r[j] = g_y2[bn + tx * 8 + j];

    #pragma unroll
    for (int i = 0; i < 8; i++) {
        float vmin = 3.4e38f;
        int   jmin = 0;
        #pragma unroll
        for (int j = 0; j < 8; j++) {
            float v = y2r[j] - 2.f * acc[i][j];   // x2 is row-constant: same argmin
            if (v < vmin) { vmin = v; jmin = bn + tx * 8 + j; }
        }
        // v > 0 always here (y2 ~ 3072 >> 2|dot|), so float-bit order == value order.
        unsigned long long key =
            ((unsigned long long)__float_as_uint(vmin) << 32) | (unsigned)jmin;
        // Reduce across the 16 threads covering this row (same ty, contiguous lanes).
        #pragma unroll
        for (int o = 8; o > 0; o >>= 1) {
            unsigned long long other = __shfl_xor_sync(0xffffffffu, key, o);
            if (other < key) key = other;     // ties -> smaller j (first occurrence)
        }
        if (tx == 0) atomicMin(&g_best[bm + ty * 8 + i], key);
    }
}

// ---------------------------------------------------------------------------
// Finalize: dist = sqrt(max(x2 + v, 0)); min-update dists, overwrite indices.
// Scalars x_idx_start / y_idx_start read on-device (graph-capture safe).
// ---------------------------------------------------------------------------
__global__ void final_kernel(const float* __restrict__ md, float* __restrict__ out,
                             int N, const int* __restrict__ xs, const int* __restrict__ ys) {
    int i = blockIdx.x * blockDim.x + threadIdx.x;
    if (i >= NB) return;
    const int x0 = xs[0];
    const int y0 = ys[0];
    unsigned long long key = g_best[i];
    float v = __uint_as_float((unsigned)(key >> 32));
    int   j = (int)(unsigned)(key & 0xffffffffULL);
    float d2   = g_x2[i] + v;
    float dist = sqrtf(fmaxf(d2, 0.f));
    float old  = md[x0 + i];
    out[x0 + i]     = fminf(dist, old);         // min with existing slice
    out[N + x0 + i] = (float)(j + y0);          // unconditional index overwrite
}

// ---------------------------------------------------------------------------
extern "C" void kernel_launch(void* const* d_in, const int* in_sizes, int n_in,
                              void* d_out, int out_size) {
    const float* x  = (const float*)d_in[0];
    const float* y  = (const float*)d_in[1];
    const float* md = (const float*)d_in[2];
    const int*   ni = (const int*)d_in[3];
    const int*   xs = (const int*)d_in[4];
    const int*   ys = (const int*)d_in[5];
    float* out = (float*)d_out;
    const int N = in_sizes[2];   // 50000

    norms_kernel<<<2 * NB, 256>>>(x, y);
    init_out_kernel<<<(N + 255) / 256, 256>>>(md, ni, out, N);
    dim3 grid(NB / 128, NB / 128);
    gemm_min_kernel<<<grid, 256>>>(x, y);
    final_kernel<<<(NB + 255) / 256, 256>>>(md, out, N, xs, ys);
}

// round 4
// speedup vs baseline: 2.4163x; 2.4163x over previous
#include <cuda_runtime.h>
#include <cuda_bf16.h>
#include <stdint.h>

#define D_DIM 3072
#define NB    4096
#define BM    128
#define BN    128
#define KC    32
#define NCHUNK (3 * D_DIM / KC)    // 288 (3 split phases)
#define STAGES 3
#define PITCH  80                  // bytes per smem row (32 bf16 = 64B + 16B pad)
#define ATILE  (BM * PITCH)        // 10240 bytes
#define STAGE_BYTES (2 * ATILE)    // A + B
#define SMEM_TOTAL (STAGES * STAGE_BYTES)   // 61440

// ---------------- scratch (no cudaMalloc allowed) ----------------
__device__ float g_x2[NB];
__device__ float g_y2[NB];
__device__ unsigned long long g_best[NB];
__device__ __nv_bfloat16 g_xhi[(size_t)NB * D_DIM];
__device__ __nv_bfloat16 g_xlo[(size_t)NB * D_DIM];
__device__ __nv_bfloat16 g_yhi[(size_t)NB * D_DIM];
__device__ __nv_bfloat16 g_ylo[(size_t)NB * D_DIM];

// ---------------- PTX helpers ----------------
__device__ __forceinline__ uint32_t smem_u32(const void* p) {
    uint32_t a;
    asm("{ .reg .u64 t; cvta.to.shared.u64 t, %1; cvt.u32.u64 %0, t; }" : "=r"(a) : "l"(p));
    return a;
}
__device__ __forceinline__ void cp_async16(uint32_t s, const void* g) {
    asm volatile("cp.async.cg.shared.global [%0], [%1], 16;\n" :: "r"(s), "l"(g) : "memory");
}
__device__ __forceinline__ void ldsm_x4(uint32_t& r0, uint32_t& r1, uint32_t& r2, uint32_t& r3,
                                        uint32_t addr) {
    asm volatile("ldmatrix.sync.aligned.m8n8.x4.shared.b16 {%0,%1,%2,%3}, [%4];"
                 : "=r"(r0), "=r"(r1), "=r"(r2), "=r"(r3) : "r"(addr));
}
__device__ __forceinline__ void mma16816(float* d, const uint32_t* a, const uint32_t* b) {
    asm volatile(
        "mma.sync.aligned.m16n8k16.row.col.f32.bf16.bf16.f32 "
        "{%0,%1,%2,%3}, {%4,%5,%6,%7}, {%8,%9}, {%0,%1,%2,%3};"
        : "+f"(d[0]), "+f"(d[1]), "+f"(d[2]), "+f"(d[3])
        : "r"(a[0]), "r"(a[1]), "r"(a[2]), "r"(a[3]), "r"(b[0]), "r"(b[1]));
}

// ---------------- split conversion: fp32 -> (bf16 hi, bf16 lo) ----------------
__global__ void convert_kernel(const float* __restrict__ x, const float* __restrict__ y) {
    size_t idx = ((size_t)blockIdx.x * blockDim.x + threadIdx.x) * 4;
    if (idx >= (size_t)NB * D_DIM) return;
    const float* src = blockIdx.y ? y : x;
    __nv_bfloat16* hi = blockIdx.y ? g_yhi : g_xhi;
    __nv_bfloat16* lo = blockIdx.y ? g_ylo : g_xlo;
    float4 v = *(const float4*)(src + idx);
    float a[4] = {v.x, v.y, v.z, v.w};
    __nv_bfloat16 h[4], l[4];
    #pragma unroll
    for (int i = 0; i < 4; i++) {
        h[i] = __float2bfloat16(a[i]);
        l[i] = __float2bfloat16(a[i] - __bfloat162float(h[i]));
    }
    ((__nv_bfloat162*)(hi + idx))[0] = __halves2bfloat162(h[0], h[1]);
    ((__nv_bfloat162*)(hi + idx))[1] = __halves2bfloat162(h[2], h[3]);
    ((__nv_bfloat162*)(lo + idx))[0] = __halves2bfloat162(l[0], l[1]);
    ((__nv_bfloat162*)(lo + idx))[1] = __halves2bfloat162(l[2], l[3]);
}

// ---------------- row squared-norms (fp32 exact) ----------------
__global__ void norms_kernel(const float* __restrict__ x, const float* __restrict__ y) {
    int row = blockIdx.x;
    const float* p = (row < NB) ? (x + (size_t)row * D_DIM) : (y + (size_t)(row - NB) * D_DIM);
    const float4* p4 = (const float4*)p;
    float s = 0.f;
    #pragma unroll 3
    for (int k = threadIdx.x; k < D_DIM / 4; k += 256) {
        float4 v = p4[k];
        s += v.x * v.x + v.y * v.y + v.z * v.z + v.w * v.w;
    }
    __shared__ float sm[256];
    sm[threadIdx.x] = s;
    __syncthreads();
    for (int o = 128; o > 0; o >>= 1) {
        if (threadIdx.x < o) sm[threadIdx.x] += sm[threadIdx.x + o];
        __syncthreads();
    }
    if (threadIdx.x == 0) {
        if (row < NB) g_x2[row] = sm[0];
        else          g_y2[row - NB] = sm[0];
    }
}

// ---------------- passthrough copy + scratch reset ----------------
__global__ void init_out_kernel(const float* __restrict__ md, const int* __restrict__ ni,
                                float* __restrict__ out, int N) {
    int i = blockIdx.x * blockDim.x + threadIdx.x;
    if (i < N) {
        out[i]     = md[i];
        out[N + i] = (float)ni[i];
    }
    if (i < NB) g_best[i] = 0xFFFFFFFFFFFFFFFFULL;
}

// ---------------- main: mma.sync bf16-split GEMM + fused min/argmin ----------------
__global__ __launch_bounds__(256, 2)
void gemm_min_kernel() {
    extern __shared__ char smem[];
    const uint32_t sb = smem_u32(smem);
    const int t   = threadIdx.x;
    const int l   = t & 31;
    const int wid = t >> 5;
    const int wm  = wid >> 2;          // 0..1 : m block of 64
    const int wn  = wid & 3;           // 0..3 : n block of 32
    const int bm  = blockIdx.y * BM;
    const int bn  = blockIdx.x * BN;

    // cp.async assignment: thread handles 2 A chunks + 2 B chunks per K-chunk
    const int r0  = t >> 2;            // 0..63
    const int c16 = t & 3;             // which 16B piece of the 64B row
    const uint32_t swOff0 = (uint32_t)r0 * PITCH + (uint32_t)c16 * 16;
    const uint32_t swOff1 = (uint32_t)(r0 + 64) * PITCH + (uint32_t)c16 * 16;
    const uint32_t gOff0  = (uint32_t)r0 * D_DIM + (uint32_t)c16 * 8;
    const uint32_t gOff1  = (uint32_t)(r0 + 64) * D_DIM + (uint32_t)c16 * 8;

    const __nv_bfloat16* Aph[3] = {g_xhi, g_xhi, g_xlo};
    const __nv_bfloat16* Bph[3] = {g_yhi, g_ylo, g_yhi};
    const size_t aBase = (size_t)bm * D_DIM;
    const size_t bBase = (size_t)bn * D_DIM;

    auto load_chunk = [&](int c) {
        int ph = c / (D_DIM / KC);
        int kk = (c % (D_DIM / KC)) * KC;
        const __nv_bfloat16* A = Aph[ph] + aBase + kk;
        const __nv_bfloat16* B = Bph[ph] + bBase + kk;
        uint32_t stage = sb + (uint32_t)(c % STAGES) * STAGE_BYTES;
        cp_async16(stage + swOff0,         A + gOff0);
        cp_async16(stage + swOff1,         A + gOff1);
        cp_async16(stage + ATILE + swOff0, B + gOff0);
        cp_async16(stage + ATILE + swOff1, B + gOff1);
        asm volatile("cp.async.commit_group;\n" ::: "memory");
    };

    load_chunk(0);
    load_chunk(1);

    // ldmatrix lane-address components (byte offsets within a stage)
    // A (row-major m16k16 frags): lane -> row wm*64 + (l%16), col (l/16)*8
    const uint32_t aLane = (uint32_t)(wm * 64 + (l & 15)) * PITCH + (uint32_t)(l >> 4) * 16;
    // B (n-major rows): group g=l/8: row wn*32 + (g>>1)*8 + (l%8), kadd (g&1)*8
    const uint32_t bLane = (uint32_t)(wn * 32 + ((l >> 4) << 3) + (l & 7)) * PITCH +
                           (uint32_t)(((l >> 3) & 1) * 16) + ATILE;

    float acc[4][4][4];
    #pragma unroll
    for (int i = 0; i < 4; i++)
        #pragma unroll
        for (int j = 0; j < 4; j++)
            #pragma unroll
            for (int q = 0; q < 4; q++) acc[i][j][q] = 0.f;

    for (int c = 0; c < NCHUNK; c++) {
        if (c < NCHUNK - 1) asm volatile("cp.async.wait_group 1;\n" ::: "memory");
        else                asm volatile("cp.async.wait_group 0;\n" ::: "memory");
        __syncthreads();
        if (c <= NCHUNK - 3) load_chunk(c + 2);

        const uint32_t stage = sb + (uint32_t)(c % STAGES) * STAGE_BYTES;
        #pragma unroll
        for (int ks = 0; ks < 2; ks++) {
            uint32_t a[4][4], b[2][4];
            #pragma unroll
            for (int i = 0; i < 4; i++)
                ldsm_x4(a[i][0], a[i][1], a[i][2], a[i][3],
                        stage + aLane + (uint32_t)i * 16 * PITCH + (uint32_t)ks * 32);
            #pragma unroll
            for (int jp = 0; jp < 2; jp++)
                ldsm_x4(b[jp][0], b[jp][1], b[jp][2], b[jp][3],
                        stage + bLane + (uint32_t)jp * 16 * PITCH + (uint32_t)ks * 32);
            #pragma unroll
            for (int i = 0; i < 4; i++) {
                #pragma unroll
                for (int jp = 0; jp < 2; jp++) {
                    mma16816(acc[i][jp * 2 + 0], a[i], &b[jp][0]);
                    mma16816(acc[i][jp * 2 + 1], a[i], &b[jp][2]);
                }
            }
        }
    }
    __syncthreads();

    // stage y2 for this column block
    float* y2s = (float*)smem;
    if (t < BN) y2s[t] = g_y2[bn + t];
    __syncthreads();

    // epilogue: lane covers rows rA = wm*64 + i*16 + l/4 and rB = rA + 8,
    // cols n = wn*32 + j*8 + 2*(l%4) (+1)
    const int nbase = wn * 32 + 2 * (l & 3);
    #pragma unroll
    for (int i = 0; i < 4; i++) {
        float vA = 3.4e38f, vB = 3.4e38f;
        int   jA = 0,       jB = 0;
        #pragma unroll
        for (int j = 0; j < 4; j++) {
            int n0 = nbase + j * 8;
            float y20 = y2s[n0], y21 = y2s[n0 + 1];
            float v;
            v = fmaf(-2.f, acc[i][j][0], y20); if (v < vA) { vA = v; jA = n0; }
            v = fmaf(-2.f, acc[i][j][1], y21); if (v < vA) { vA = v; jA = n0 + 1; }
            v = fmaf(-2.f, acc[i][j][2], y20); if (v < vB) { vB = v; jB = n0; }
            v = fmaf(-2.f, acc[i][j][3], y21); if (v < vB) { vB = v; jB = n0 + 1; }
        }
        unsigned long long keyA =
            ((unsigned long long)__float_as_uint(vA) << 32) | (unsigned)(bn + jA);
        unsigned long long keyB =
            ((unsigned long long)__float_as_uint(vB) << 32) | (unsigned)(bn + jB);
        #pragma unroll
        for (int o = 1; o < 4; o <<= 1) {     // reduce across the 4 lanes sharing a row
            unsigned long long oA = __shfl_xor_sync(0xffffffffu, keyA, o);
            unsigned long long oB = __shfl_xor_sync(0xffffffffu, keyB, o);
            if (oA < keyA) keyA = oA;
            if (oB < keyB) keyB = oB;
        }
        if ((l & 3) == 0) {
            int rA = bm + wm * 64 + i * 16 + (l >> 2);
            atomicMin(&g_best[rA],     keyA);
            atomicMin(&g_best[rA + 8], keyB);
        }
    }
}

// ---------------- finalize ----------------
__global__ void final_kernel(const float* __restrict__ md, float* __restrict__ out,
                             int N, const int* __restrict__ xs, const int* __restrict__ ys) {
    int i = blockIdx.x * blockDim.x + threadIdx.x;
    if (i >= NB) return;
    const int x0 = xs[0];
    const int y0 = ys[0];
    unsigned long long key = g_best[i];
    float v = __uint_as_float((unsigned)(key >> 32));
    int   j = (int)(unsigned)(key & 0xffffffffULL);
    float dist = sqrtf(fmaxf(g_x2[i] + v, 0.f));
    float old  = md[x0 + i];
    out[x0 + i]     = fminf(dist, old);
    out[N + x0 + i] = (float)(j + y0);
}

// ---------------- launch ----------------
extern "C" void kernel_launch(void* const* d_in, const int* in_sizes, int n_in,
                              void* d_out, int out_size) {
    const float* x  = (const float*)d_in[0];
    const float* y  = (const float*)d_in[1];
    const float* md = (const float*)d_in[2];
    const int*   ni = (const int*)d_in[3];
    const int*   xs = (const int*)d_in[4];
    const int*   ys = (const int*)d_in[5];
    float* out = (float*)d_out;
    const int N = in_sizes[2];   // 50000

    cudaFuncSetAttribute(gemm_min_kernel,
                         cudaFuncAttributeMaxDynamicSharedMemorySize, SMEM_TOTAL);

    dim3 cgrid(((size_t)NB * D_DIM / 4 + 255) / 256, 2);
    convert_kernel<<<cgrid, 256>>>(x, y);
    norms_kernel<<<2 * NB, 256>>>(x, y);
    init_out_kernel<<<(N + 255) / 256, 256>>>(md, ni, out, N);
    dim3 grid(NB / BN, NB / BM);
    gemm_min_kernel<<<grid, 256, SMEM_TOTAL>>>();
    final_kernel<<<(NB + 255) / 256, 256>>>(md, out, N, xs, ys);
}